// round 8
// baseline (speedup 1.0000x reference)
#include <cuda_runtime.h>
#include <cuda_fp16.h>
#include <cstdint>

// ============================================================================
// Problem dims
// ============================================================================
static constexpr int M_TOTAL = 8192;      // B*S = 4*2048
static constexpr int N_TOTAL = 11008;     // D_OUT
static constexpr int K_TOTAL = 4096;      // D_IN

static constexpr int M_TILE = 128;
static constexpr int N_TILE = 128;
static constexpr int K_TILE = 64;         // 64 fp16 = 128B rows (SW128 atom)
static constexpr int STAGES = 3;
static constexpr int K_STEPS = K_TOTAL / K_TILE;   // 64
static constexpr int M_TILES = M_TOTAL / M_TILE;   // 64
static constexpr int N_TILES = N_TOTAL / N_TILE;   // 86
static constexpr int THREADS = 256;                // 8 warps: 2(m) x 4(n), warp tile 64x32

// SMEM stage: A 128x128B = 16KB, B 128x128B = 16KB
static constexpr int A_STAGE_BYTES = M_TILE * 128;           // 16384
static constexpr int B_STAGE_BYTES = N_TILE * 128;           // 16384
static constexpr int STAGE_BYTES = A_STAGE_BYTES + B_STAGE_BYTES;  // 32768
static constexpr int SMEM_BYTES = STAGES * STAGE_BYTES;      // 98304 -> 2 CTAs/SM

// ============================================================================
// Scratch (device globals — no allocation allowed)
// ============================================================================
__device__ __half g_xh[(size_t)M_TOTAL * K_TOTAL];   // 64 MB fp16 x
__device__ __half g_wh[(size_t)N_TOTAL * K_TOTAL];   // 86 MB fp16 w (exact from e4m3)

// ============================================================================
// Helpers
// ============================================================================
__device__ __forceinline__ uint32_t smem_to_u32(const void* p) {
    uint32_t a;
    asm("{ .reg .u64 t; cvta.to.shared.u64 t, %1; cvt.u32.u64 %0, t; }" : "=r"(a) : "l"(p));
    return a;
}

#define SW128(o) ((o) ^ (((o) >> 3) & 0x70))

__device__ __forceinline__ void cp_async16(uint32_t dst, const void* src) {
    unsigned long long g = (unsigned long long)__cvta_generic_to_global(src);
    asm volatile("cp.async.cg.shared.global [%0], [%1], 16;" :: "r"(dst), "l"(g) : "memory");
}
#define CP_COMMIT() asm volatile("cp.async.commit_group;" ::: "memory")
#define CP_WAIT_GROUP(n) asm volatile("cp.async.wait_group %0;" :: "n"(n) : "memory")

__device__ __forceinline__ void ldsm_x4(uint32_t& r0, uint32_t& r1, uint32_t& r2, uint32_t& r3,
                                        uint32_t addr) {
    asm volatile("ldmatrix.sync.aligned.m8n8.x4.shared.b16 {%0,%1,%2,%3}, [%4];"
                 : "=r"(r0), "=r"(r1), "=r"(r2), "=r"(r3) : "r"(addr));
}

__device__ __forceinline__ void mma_16816(float& c0, float& c1, float& c2, float& c3,
                                          uint32_t a0, uint32_t a1, uint32_t a2, uint32_t a3,
                                          uint32_t b0, uint32_t b1) {
    asm volatile("mma.sync.aligned.m16n8k16.row.col.f32.f16.f16.f32 "
                 "{%0,%1,%2,%3}, {%4,%5,%6,%7}, {%8,%9}, {%0,%1,%2,%3};"
                 : "+f"(c0), "+f"(c1), "+f"(c2), "+f"(c3)
                 : "r"(a0), "r"(a1), "r"(a2), "r"(a3), "r"(b0), "r"(b1));
}

// ============================================================================
// Merged prep: fp32 -> fp16 for x (rounds, rel <= 2^-11) and w (exact e4m3)
// ============================================================================
__global__ void k_prep(const float4* __restrict__ x, const float4* __restrict__ w,
                       int n4x, int n4w) {
    int i = blockIdx.x * 256 + threadIdx.x;
    const float4* src;
    uint2* dst;
    if (i < n4x) {
        src = x + i;
        dst = reinterpret_cast<uint2*>(g_xh) + i;
    } else {
        int j = i - n4x;
        if (j >= n4w) return;
        src = w + j;
        dst = reinterpret_cast<uint2*>(g_wh) + j;
    }
    float4 v = *src;
    union { __half h[4]; uint2 u; } p;
    p.h[0] = __float2half_rn(v.x); p.h[1] = __float2half_rn(v.y);
    p.h[2] = __float2half_rn(v.z); p.h[3] = __float2half_rn(v.w);
    *dst = p.u;
}

// ============================================================================
// GEMM: out[m,n] = sum_k x[m,k]*w[n,k] * scale[n] + bias[n]
// CTA tile 128x128, 8 warps (2m x 4n), warp tile 64x32, 2 CTAs/SM.
// ============================================================================
__global__ __launch_bounds__(THREADS, 2)
void k_gemm(const float* __restrict__ scale, const float* __restrict__ bias,
            float* __restrict__ out) {
    extern __shared__ char smem[];
    const uint32_t smem_u = smem_to_u32(smem);
    const int tid = threadIdx.x;
    const int lane = tid & 31;
    const int wid = tid >> 5;
    const int warp_m = wid >> 2;       // 0..1 -> 64-row slabs
    const int warp_n = wid & 3;        // 0..3 -> 32-col slabs

    // Tile mapping with GROUP=8 m-swizzle for L2 locality
    const int GROUP = 8;
    int bid = blockIdx.x;
    int tpg = GROUP * N_TILES;
    int g = bid / tpg;
    int rem = bid % tpg;
    const int m0 = (g * GROUP + (rem % GROUP)) * M_TILE;
    const int n0 = (rem / GROUP) * N_TILE;

    // ---- producer: fill stage (j % STAGES) with k-tile j ----
    auto produce = [&](int j) {
        const size_t k0 = (size_t)j * K_TILE;
        const uint32_t st = smem_u + (uint32_t)(j % STAGES) * STAGE_BYTES;
        // A: 128 rows x 8 16B-chunks = 1024 chunks, 4 per thread
#pragma unroll
        for (int q = 0; q < 4; q++) {
            int cid = tid + q * THREADS;
            int row = cid >> 3, ch = cid & 7;
            uint32_t off = SW128((uint32_t)(row * 128 + ch * 16));
            const char* s = (const char*)(g_xh + (size_t)(m0 + row) * K_TOTAL + k0) + ch * 16;
            cp_async16(st + off, s);
        }
        // B: 128 rows x 8 chunks = 1024 chunks, 4 per thread
#pragma unroll
        for (int q = 0; q < 4; q++) {
            int cid = tid + q * THREADS;
            int row = cid >> 3, ch = cid & 7;
            uint32_t off = SW128((uint32_t)(row * 128 + ch * 16));
            const char* s = (const char*)(g_wh + (size_t)(n0 + row) * K_TOTAL + k0) + ch * 16;
            cp_async16(st + (uint32_t)A_STAGE_BYTES + off, s);
        }
    };

    float c[4][4][4];   // [mi][ni][reg] = 64 regs
#pragma unroll
    for (int mi = 0; mi < 4; mi++)
#pragma unroll
        for (int ni = 0; ni < 4; ni++)
#pragma unroll
            for (int r = 0; r < 4; r++) c[mi][ni][r] = 0.0f;

    // prologue: fill 2 of 3 stages
    produce(0); CP_COMMIT();
    produce(1); CP_COMMIT();

    // Per-lane static pieces of ldmatrix addressing (validated in rounds 2-3)
    const int a_row_l = (lane & 7) + ((lane >> 3) & 1) * 8;   // within m16 tile
    const int a_kb_l  = ((lane >> 4) & 1) * 16;               // 0 or 16 bytes
    const int b_row_l = (lane & 7) + ((lane >> 4) & 1) * 8;   // within n16 block
    const int b_kb_l  = ((lane >> 3) & 1) * 16;

#pragma unroll 1
    for (int i = 0; i < K_STEPS; i++) {
        CP_WAIT_GROUP(1);        // k-tile i resident
        __syncthreads();         // all fills visible; all warps done with stage i-1

        int j = i + (STAGES - 1);
        if (j < K_STEPS) produce(j);
        CP_COMMIT();             // unconditional (possibly-empty group keeps count)

        const uint32_t stA = smem_u + (uint32_t)(i % STAGES) * STAGE_BYTES;
        const uint32_t stB = stA + (uint32_t)A_STAGE_BYTES;

#pragma unroll
        for (int ks = 0; ks < 4; ks++) {        // four k16 sub-steps in the 64-k tile
            uint32_t a[4][4];
#pragma unroll
            for (int mi = 0; mi < 4; mi++) {
                int row = warp_m * 64 + mi * 16 + a_row_l;
                uint32_t o = (uint32_t)(row * 128 + ks * 32 + a_kb_l);
                ldsm_x4(a[mi][0], a[mi][1], a[mi][2], a[mi][3], stA + SW128(o));
            }
            uint32_t b[2][4];
#pragma unroll
            for (int nb = 0; nb < 2; nb++) {
                int row = warp_n * 32 + nb * 16 + b_row_l;
                uint32_t o = (uint32_t)(row * 128 + ks * 32 + b_kb_l);
                ldsm_x4(b[nb][0], b[nb][1], b[nb][2], b[nb][3], stB + SW128(o));
            }
#pragma unroll
            for (int mi = 0; mi < 4; mi++) {
#pragma unroll
                for (int ni = 0; ni < 4; ni++) {
                    uint32_t b0 = b[ni >> 1][(ni & 1) * 2 + 0];
                    uint32_t b1 = b[ni >> 1][(ni & 1) * 2 + 1];
                    mma_16816(c[mi][ni][0], c[mi][ni][1], c[mi][ni][2], c[mi][ni][3],
                              a[mi][0], a[mi][1], a[mi][2], a[mi][3], b0, b1);
                }
            }
        }
    }

    // ---- epilogue: out = c * scale[n] + bias[n] ----
    const int col_base = n0 + warp_n * 32 + (lane & 3) * 2;
    const int row_base = m0 + warp_m * 64 + (lane >> 2);
#pragma unroll
    for (int ni = 0; ni < 4; ni++) {
        int col = col_base + ni * 8;
        float s0 = scale[col], s1 = scale[col + 1];
        float b0 = bias[col],  b1 = bias[col + 1];
#pragma unroll
        for (int mi = 0; mi < 4; mi++) {
            int r = row_base + mi * 16;
            float2 v0 = make_float2(c[mi][ni][0] * s0 + b0, c[mi][ni][1] * s1 + b1);
            float2 v1 = make_float2(c[mi][ni][2] * s0 + b0, c[mi][ni][3] * s1 + b1);
            *reinterpret_cast<float2*>(out + (size_t)r * N_TOTAL + col) = v0;
            *reinterpret_cast<float2*>(out + (size_t)(r + 8) * N_TOTAL + col) = v1;
        }
    }
}

// ============================================================================
// kernel_launch
// ============================================================================
extern "C" void kernel_launch(void* const* d_in, const int* in_sizes, int n_in,
                              void* d_out, int out_size) {
    const float* x     = (const float*)d_in[0];  // [4, 2048, 4096]
    const float* w_q   = (const float*)d_in[1];  // [11008, 4096]
    const float* scale = (const float*)d_in[2];  // [11008, 1]
    const float* bias  = (const float*)d_in[3];  // [11008]
    float* out = (float*)d_out;                  // [4, 2048, 11008]

    int n4x = M_TOTAL * (K_TOTAL / 4);           // 8,388,608
    int n4w = N_TOTAL * (K_TOTAL / 4);           // 11,272,192
    int n4 = n4x + n4w;
    k_prep<<<(n4 + 255) / 256, 256>>>((const float4*)x, (const float4*)w_q, n4x, n4w);

    cudaFuncSetAttribute(k_gemm, cudaFuncAttributeMaxDynamicSharedMemorySize, SMEM_BYTES);
    k_gemm<<<M_TILES * N_TILES, THREADS, SMEM_BYTES>>>(scale, bias, out);
}

// round 9
// speedup vs baseline: 1.0005x; 1.0005x over previous
#include <cuda_runtime.h>
#include <cuda_fp16.h>
#include <cstdint>

// ============================================================================
// Problem dims
// ============================================================================
static constexpr int M_TOTAL = 8192;      // B*S = 4*2048
static constexpr int N_TOTAL = 11008;     // D_OUT
static constexpr int K_TOTAL = 4096;      // D_IN

static constexpr int M_TILE = 128;
static constexpr int N_TILE = 128;
static constexpr int K_TILE = 64;         // 64 fp16 = 128B rows (SW128 atom)
static constexpr int STAGES = 3;
static constexpr int K_STEPS = K_TOTAL / K_TILE;   // 64
static constexpr int M_TILES = M_TOTAL / M_TILE;   // 64
static constexpr int N_TILES = N_TOTAL / N_TILE;   // 86
static constexpr int THREADS = 256;                // 8 warps: 2(m) x 4(n), warp tile 64x32

// SMEM stage: A 128x128B = 16KB, B 128x128B = 16KB
static constexpr int A_STAGE_BYTES = M_TILE * 128;           // 16384
static constexpr int B_STAGE_BYTES = N_TILE * 128;           // 16384
static constexpr int STAGE_BYTES = A_STAGE_BYTES + B_STAGE_BYTES;  // 32768
static constexpr int SMEM_BYTES = STAGES * STAGE_BYTES;      // 98304 -> 2 CTAs/SM

// ============================================================================
// Scratch (device globals — no allocation allowed)
// ============================================================================
__device__ __half g_xh[(size_t)M_TOTAL * K_TOTAL];   // 64 MB fp16 x
__device__ __half g_wh[(size_t)N_TOTAL * K_TOTAL];   // 86 MB fp16 w (exact from e4m3)

// ============================================================================
// Helpers
// ============================================================================
__device__ __forceinline__ uint32_t smem_to_u32(const void* p) {
    uint32_t a;
    asm("{ .reg .u64 t; cvta.to.shared.u64 t, %1; cvt.u32.u64 %0, t; }" : "=r"(a) : "l"(p));
    return a;
}

#define SW128(o) ((o) ^ (((o) >> 3) & 0x70))

__device__ __forceinline__ void cp_async16(uint32_t dst, const void* src) {
    unsigned long long g = (unsigned long long)__cvta_generic_to_global(src);
    asm volatile("cp.async.cg.shared.global [%0], [%1], 16;" :: "r"(dst), "l"(g) : "memory");
}
#define CP_COMMIT() asm volatile("cp.async.commit_group;" ::: "memory")
#define CP_WAIT_GROUP(n) asm volatile("cp.async.wait_group %0;" :: "n"(n) : "memory")

__device__ __forceinline__ void ldsm_x4(uint32_t& r0, uint32_t& r1, uint32_t& r2, uint32_t& r3,
                                        uint32_t addr) {
    asm volatile("ldmatrix.sync.aligned.m8n8.x4.shared.b16 {%0,%1,%2,%3}, [%4];"
                 : "=r"(r0), "=r"(r1), "=r"(r2), "=r"(r3) : "r"(addr));
}

__device__ __forceinline__ void mma_16816(float& c0, float& c1, float& c2, float& c3,
                                          uint32_t a0, uint32_t a1, uint32_t a2, uint32_t a3,
                                          uint32_t b0, uint32_t b1) {
    asm volatile("mma.sync.aligned.m16n8k16.row.col.f32.f16.f16.f32 "
                 "{%0,%1,%2,%3}, {%4,%5,%6,%7}, {%8,%9}, {%0,%1,%2,%3};"
                 : "+f"(c0), "+f"(c1), "+f"(c2), "+f"(c3)
                 : "r"(a0), "r"(a1), "r"(a2), "r"(a3), "r"(b0), "r"(b1));
}

// ============================================================================
// Merged prep: fp32 -> fp16 for x (rounds, rel <= 2^-11) and w (exact e4m3)
// ============================================================================
__global__ void k_prep(const float4* __restrict__ x, const float4* __restrict__ w,
                       int n4x, int n4w) {
    int i = blockIdx.x * 256 + threadIdx.x;
    const float4* src;
    uint2* dst;
    if (i < n4x) {
        src = x + i;
        dst = reinterpret_cast<uint2*>(g_xh) + i;
    } else {
        int j = i - n4x;
        if (j >= n4w) return;
        src = w + j;
        dst = reinterpret_cast<uint2*>(g_wh) + j;
    }
    float4 v = *src;
    union { __half h[4]; uint2 u; } p;
    p.h[0] = __float2half_rn(v.x); p.h[1] = __float2half_rn(v.y);
    p.h[2] = __float2half_rn(v.z); p.h[3] = __float2half_rn(v.w);
    *dst = p.u;
}

// ============================================================================
// GEMM: out[m,n] = sum_k x[m,k]*w[n,k] * scale[n] + bias[n]
// CTA tile 128x128, 8 warps (2m x 4n), warp tile 64x32, 2 CTAs/SM.
// ============================================================================
__global__ __launch_bounds__(THREADS, 2)
void k_gemm(const float* __restrict__ scale, const float* __restrict__ bias,
            float* __restrict__ out) {
    extern __shared__ char smem[];
    const uint32_t smem_u = smem_to_u32(smem);
    const int tid = threadIdx.x;
    const int lane = tid & 31;
    const int wid = tid >> 5;
    const int warp_m = wid >> 2;       // 0..1 -> 64-row slabs
    const int warp_n = wid & 3;        // 0..3 -> 32-col slabs

    // Tile mapping with GROUP=8 m-swizzle for L2 locality
    const int GROUP = 8;
    int bid = blockIdx.x;
    int tpg = GROUP * N_TILES;
    int g = bid / tpg;
    int rem = bid % tpg;
    const int m0 = (g * GROUP + (rem % GROUP)) * M_TILE;
    const int n0 = (rem / GROUP) * N_TILE;

    // ---- producer: fill stage (j % STAGES) with k-tile j ----
    auto produce = [&](int j) {
        const size_t k0 = (size_t)j * K_TILE;
        const uint32_t st = smem_u + (uint32_t)(j % STAGES) * STAGE_BYTES;
        // A: 128 rows x 8 16B-chunks = 1024 chunks, 4 per thread
#pragma unroll
        for (int q = 0; q < 4; q++) {
            int cid = tid + q * THREADS;
            int row = cid >> 3, ch = cid & 7;
            uint32_t off = SW128((uint32_t)(row * 128 + ch * 16));
            const char* s = (const char*)(g_xh + (size_t)(m0 + row) * K_TOTAL + k0) + ch * 16;
            cp_async16(st + off, s);
        }
        // B: 128 rows x 8 chunks = 1024 chunks, 4 per thread
#pragma unroll
        for (int q = 0; q < 4; q++) {
            int cid = tid + q * THREADS;
            int row = cid >> 3, ch = cid & 7;
            uint32_t off = SW128((uint32_t)(row * 128 + ch * 16));
            const char* s = (const char*)(g_wh + (size_t)(n0 + row) * K_TOTAL + k0) + ch * 16;
            cp_async16(st + (uint32_t)A_STAGE_BYTES + off, s);
        }
    };

    float c[4][4][4];   // [mi][ni][reg] = 64 regs
#pragma unroll
    for (int mi = 0; mi < 4; mi++)
#pragma unroll
        for (int ni = 0; ni < 4; ni++)
#pragma unroll
            for (int r = 0; r < 4; r++) c[mi][ni][r] = 0.0f;

    // prologue: fill 2 of 3 stages
    produce(0); CP_COMMIT();
    produce(1); CP_COMMIT();

    // Per-lane static pieces of ldmatrix addressing (validated in rounds 2-3)
    const int a_row_l = (lane & 7) + ((lane >> 3) & 1) * 8;   // within m16 tile
    const int a_kb_l  = ((lane >> 4) & 1) * 16;               // 0 or 16 bytes
    const int b_row_l = (lane & 7) + ((lane >> 4) & 1) * 8;   // within n16 block
    const int b_kb_l  = ((lane >> 3) & 1) * 16;

#pragma unroll 1
    for (int i = 0; i < K_STEPS; i++) {
        CP_WAIT_GROUP(1);        // k-tile i resident
        __syncthreads();         // all fills visible; all warps done with stage i-1

        int j = i + (STAGES - 1);
        if (j < K_STEPS) produce(j);
        CP_COMMIT();             // unconditional (possibly-empty group keeps count)

        const uint32_t stA = smem_u + (uint32_t)(i % STAGES) * STAGE_BYTES;
        const uint32_t stB = stA + (uint32_t)A_STAGE_BYTES;

#pragma unroll
        for (int ks = 0; ks < 4; ks++) {        // four k16 sub-steps in the 64-k tile
            uint32_t a[4][4];
#pragma unroll
            for (int mi = 0; mi < 4; mi++) {
                int row = warp_m * 64 + mi * 16 + a_row_l;
                uint32_t o = (uint32_t)(row * 128 + ks * 32 + a_kb_l);
                ldsm_x4(a[mi][0], a[mi][1], a[mi][2], a[mi][3], stA + SW128(o));
            }
            uint32_t b[2][4];
#pragma unroll
            for (int nb = 0; nb < 2; nb++) {
                int row = warp_n * 32 + nb * 16 + b_row_l;
                uint32_t o = (uint32_t)(row * 128 + ks * 32 + b_kb_l);
                ldsm_x4(b[nb][0], b[nb][1], b[nb][2], b[nb][3], stB + SW128(o));
            }
#pragma unroll
            for (int mi = 0; mi < 4; mi++) {
#pragma unroll
                for (int ni = 0; ni < 4; ni++) {
                    uint32_t b0 = b[ni >> 1][(ni & 1) * 2 + 0];
                    uint32_t b1 = b[ni >> 1][(ni & 1) * 2 + 1];
                    mma_16816(c[mi][ni][0], c[mi][ni][1], c[mi][ni][2], c[mi][ni][3],
                              a[mi][0], a[mi][1], a[mi][2], a[mi][3], b0, b1);
                }
            }
        }
    }

    // ---- epilogue: out = c * scale[n] + bias[n] ----
    const int col_base = n0 + warp_n * 32 + (lane & 3) * 2;
    const int row_base = m0 + warp_m * 64 + (lane >> 2);
#pragma unroll
    for (int ni = 0; ni < 4; ni++) {
        int col = col_base + ni * 8;
        float s0 = scale[col], s1 = scale[col + 1];
        float b0 = bias[col],  b1 = bias[col + 1];
#pragma unroll
        for (int mi = 0; mi < 4; mi++) {
            int r = row_base + mi * 16;
            float2 v0 = make_float2(c[mi][ni][0] * s0 + b0, c[mi][ni][1] * s1 + b1);
            float2 v1 = make_float2(c[mi][ni][2] * s0 + b0, c[mi][ni][3] * s1 + b1);
            *reinterpret_cast<float2*>(out + (size_t)r * N_TOTAL + col) = v0;
            *reinterpret_cast<float2*>(out + (size_t)(r + 8) * N_TOTAL + col) = v1;
        }
    }
}

// ============================================================================
// kernel_launch
// ============================================================================
extern "C" void kernel_launch(void* const* d_in, const int* in_sizes, int n_in,
                              void* d_out, int out_size) {
    const float* x     = (const float*)d_in[0];  // [4, 2048, 4096]
    const float* w_q   = (const float*)d_in[1];  // [11008, 4096]
    const float* scale = (const float*)d_in[2];  // [11008, 1]
    const float* bias  = (const float*)d_in[3];  // [11008]
    float* out = (float*)d_out;                  // [4, 2048, 11008]

    int n4x = M_TOTAL * (K_TOTAL / 4);           // 8,388,608
    int n4w = N_TOTAL * (K_TOTAL / 4);           // 11,272,192
    int n4 = n4x + n4w;
    k_prep<<<(n4 + 255) / 256, 256>>>((const float4*)x, (const float4*)w_q, n4x, n4w);

    cudaFuncSetAttribute(k_gemm, cudaFuncAttributeMaxDynamicSharedMemorySize, SMEM_BYTES);
    k_gemm<<<M_TILES * N_TILES, THREADS, SMEM_BYTES>>>(scale, bias, out);
}

// round 10
// speedup vs baseline: 1.0007x; 1.0003x over previous
#include <cuda_runtime.h>
#include <cuda_fp16.h>
#include <cstdint>

// ============================================================================
// Problem dims
// ============================================================================
static constexpr int M_TOTAL = 8192;      // B*S = 4*2048
static constexpr int N_TOTAL = 11008;     // D_OUT
static constexpr int K_TOTAL = 4096;      // D_IN

static constexpr int M_TILE = 128;
static constexpr int N_TILE = 128;
static constexpr int K_TILE = 64;         // 64 fp16 = 128B rows (SW128 atom)
static constexpr int STAGES = 3;
static constexpr int K_STEPS = K_TOTAL / K_TILE;   // 64
static constexpr int M_TILES = M_TOTAL / M_TILE;   // 64
static constexpr int N_TILES = N_TOTAL / N_TILE;   // 86
static constexpr int THREADS = 256;                // 8 warps: 2(m) x 4(n), warp tile 64x32

// SMEM stage: A 128x128B = 16KB, B 128x128B = 16KB
static constexpr int A_STAGE_BYTES = M_TILE * 128;           // 16384
static constexpr int B_STAGE_BYTES = N_TILE * 128;           // 16384
static constexpr int STAGE_BYTES = A_STAGE_BYTES + B_STAGE_BYTES;  // 32768
static constexpr int SMEM_BYTES = STAGES * STAGE_BYTES;      // 98304 -> 2 CTAs/SM

// ============================================================================
// Scratch (device globals — no allocation allowed)
// ============================================================================
__device__ __half g_xh[(size_t)M_TOTAL * K_TOTAL];   // 64 MB fp16 x
__device__ __half g_wh[(size_t)N_TOTAL * K_TOTAL];   // 86 MB fp16 w (exact from e4m3)

// ============================================================================
// Helpers
// ============================================================================
__device__ __forceinline__ uint32_t smem_to_u32(const void* p) {
    uint32_t a;
    asm("{ .reg .u64 t; cvta.to.shared.u64 t, %1; cvt.u32.u64 %0, t; }" : "=r"(a) : "l"(p));
    return a;
}

#define SW128(o) ((o) ^ (((o) >> 3) & 0x70))

__device__ __forceinline__ void cp_async16(uint32_t dst, const void* src) {
    unsigned long long g = (unsigned long long)__cvta_generic_to_global(src);
    asm volatile("cp.async.cg.shared.global [%0], [%1], 16;" :: "r"(dst), "l"(g) : "memory");
}
#define CP_COMMIT() asm volatile("cp.async.commit_group;" ::: "memory")
#define CP_WAIT_GROUP(n) asm volatile("cp.async.wait_group %0;" :: "n"(n) : "memory")

__device__ __forceinline__ void ldsm_x4(uint32_t& r0, uint32_t& r1, uint32_t& r2, uint32_t& r3,
                                        uint32_t addr) {
    asm volatile("ldmatrix.sync.aligned.m8n8.x4.shared.b16 {%0,%1,%2,%3}, [%4];"
                 : "=r"(r0), "=r"(r1), "=r"(r2), "=r"(r3) : "r"(addr));
}

__device__ __forceinline__ void mma_16816(float& c0, float& c1, float& c2, float& c3,
                                          uint32_t a0, uint32_t a1, uint32_t a2, uint32_t a3,
                                          uint32_t b0, uint32_t b1) {
    asm volatile("mma.sync.aligned.m16n8k16.row.col.f32.f16.f16.f32 "
                 "{%0,%1,%2,%3}, {%4,%5,%6,%7}, {%8,%9}, {%0,%1,%2,%3};"
                 : "+f"(c0), "+f"(c1), "+f"(c2), "+f"(c3)
                 : "r"(a0), "r"(a1), "r"(a2), "r"(a3), "r"(b0), "r"(b1));
}

// ============================================================================
// Merged prep: fp32 -> fp16 for x (rounds, rel <= 2^-11) and w (exact e4m3)
// ============================================================================
__global__ void k_prep(const float4* __restrict__ x, const float4* __restrict__ w,
                       int n4x, int n4w) {
    int i = blockIdx.x * 256 + threadIdx.x;
    const float4* src;
    uint2* dst;
    if (i < n4x) {
        src = x + i;
        dst = reinterpret_cast<uint2*>(g_xh) + i;
    } else {
        int j = i - n4x;
        if (j >= n4w) return;
        src = w + j;
        dst = reinterpret_cast<uint2*>(g_wh) + j;
    }
    float4 v = *src;
    union { __half h[4]; uint2 u; } p;
    p.h[0] = __float2half_rn(v.x); p.h[1] = __float2half_rn(v.y);
    p.h[2] = __float2half_rn(v.z); p.h[3] = __float2half_rn(v.w);
    *dst = p.u;
}

// ============================================================================
// GEMM: out[m,n] = sum_k x[m,k]*w[n,k] * scale[n] + bias[n]
// CTA tile 128x128, 8 warps (2m x 4n), warp tile 64x32, 2 CTAs/SM.
// ============================================================================
__global__ __launch_bounds__(THREADS, 2)
void k_gemm(const float* __restrict__ scale, const float* __restrict__ bias,
            float* __restrict__ out) {
    extern __shared__ char smem[];
    const uint32_t smem_u = smem_to_u32(smem);
    const int tid = threadIdx.x;
    const int lane = tid & 31;
    const int wid = tid >> 5;
    const int warp_m = wid >> 2;       // 0..1 -> 64-row slabs
    const int warp_n = wid & 3;        // 0..3 -> 32-col slabs

    // Tile mapping with GROUP=8 m-swizzle for L2 locality
    const int GROUP = 8;
    int bid = blockIdx.x;
    int tpg = GROUP * N_TILES;
    int g = bid / tpg;
    int rem = bid % tpg;
    const int m0 = (g * GROUP + (rem % GROUP)) * M_TILE;
    const int n0 = (rem / GROUP) * N_TILE;

    // ---- producer: fill stage (j % STAGES) with k-tile j ----
    auto produce = [&](int j) {
        const size_t k0 = (size_t)j * K_TILE;
        const uint32_t st = smem_u + (uint32_t)(j % STAGES) * STAGE_BYTES;
        // A: 128 rows x 8 16B-chunks = 1024 chunks, 4 per thread
#pragma unroll
        for (int q = 0; q < 4; q++) {
            int cid = tid + q * THREADS;
            int row = cid >> 3, ch = cid & 7;
            uint32_t off = SW128((uint32_t)(row * 128 + ch * 16));
            const char* s = (const char*)(g_xh + (size_t)(m0 + row) * K_TOTAL + k0) + ch * 16;
            cp_async16(st + off, s);
        }
        // B: 128 rows x 8 chunks = 1024 chunks, 4 per thread
#pragma unroll
        for (int q = 0; q < 4; q++) {
            int cid = tid + q * THREADS;
            int row = cid >> 3, ch = cid & 7;
            uint32_t off = SW128((uint32_t)(row * 128 + ch * 16));
            const char* s = (const char*)(g_wh + (size_t)(n0 + row) * K_TOTAL + k0) + ch * 16;
            cp_async16(st + (uint32_t)A_STAGE_BYTES + off, s);
        }
    };

    float c[4][4][4];   // [mi][ni][reg] = 64 regs
#pragma unroll
    for (int mi = 0; mi < 4; mi++)
#pragma unroll
        for (int ni = 0; ni < 4; ni++)
#pragma unroll
            for (int r = 0; r < 4; r++) c[mi][ni][r] = 0.0f;

    // prologue: fill 2 of 3 stages
    produce(0); CP_COMMIT();
    produce(1); CP_COMMIT();

    // Per-lane static pieces of ldmatrix addressing (validated in rounds 2-3)
    const int a_row_l = (lane & 7) + ((lane >> 3) & 1) * 8;   // within m16 tile
    const int a_kb_l  = ((lane >> 4) & 1) * 16;               // 0 or 16 bytes
    const int b_row_l = (lane & 7) + ((lane >> 4) & 1) * 8;   // within n16 block
    const int b_kb_l  = ((lane >> 3) & 1) * 16;

#pragma unroll 1
    for (int i = 0; i < K_STEPS; i++) {
        CP_WAIT_GROUP(1);        // k-tile i resident
        __syncthreads();         // all fills visible; all warps done with stage i-1

        int j = i + (STAGES - 1);
        if (j < K_STEPS) produce(j);
        CP_COMMIT();             // unconditional (possibly-empty group keeps count)

        const uint32_t stA = smem_u + (uint32_t)(i % STAGES) * STAGE_BYTES;
        const uint32_t stB = stA + (uint32_t)A_STAGE_BYTES;

#pragma unroll
        for (int ks = 0; ks < 4; ks++) {        // four k16 sub-steps in the 64-k tile
            uint32_t a[4][4];
#pragma unroll
            for (int mi = 0; mi < 4; mi++) {
                int row = warp_m * 64 + mi * 16 + a_row_l;
                uint32_t o = (uint32_t)(row * 128 + ks * 32 + a_kb_l);
                ldsm_x4(a[mi][0], a[mi][1], a[mi][2], a[mi][3], stA + SW128(o));
            }
            uint32_t b[2][4];
#pragma unroll
            for (int nb = 0; nb < 2; nb++) {
                int row = warp_n * 32 + nb * 16 + b_row_l;
                uint32_t o = (uint32_t)(row * 128 + ks * 32 + b_kb_l);
                ldsm_x4(b[nb][0], b[nb][1], b[nb][2], b[nb][3], stB + SW128(o));
            }
#pragma unroll
            for (int mi = 0; mi < 4; mi++) {
#pragma unroll
                for (int ni = 0; ni < 4; ni++) {
                    uint32_t b0 = b[ni >> 1][(ni & 1) * 2 + 0];
                    uint32_t b1 = b[ni >> 1][(ni & 1) * 2 + 1];
                    mma_16816(c[mi][ni][0], c[mi][ni][1], c[mi][ni][2], c[mi][ni][3],
                              a[mi][0], a[mi][1], a[mi][2], a[mi][3], b0, b1);
                }
            }
        }
    }

    // ---- epilogue: out = c * scale[n] + bias[n] ----
    const int col_base = n0 + warp_n * 32 + (lane & 3) * 2;
    const int row_base = m0 + warp_m * 64 + (lane >> 2);
#pragma unroll
    for (int ni = 0; ni < 4; ni++) {
        int col = col_base + ni * 8;
        float s0 = scale[col], s1 = scale[col + 1];
        float b0 = bias[col],  b1 = bias[col + 1];
#pragma unroll
        for (int mi = 0; mi < 4; mi++) {
            int r = row_base + mi * 16;
            float2 v0 = make_float2(c[mi][ni][0] * s0 + b0, c[mi][ni][1] * s1 + b1);
            float2 v1 = make_float2(c[mi][ni][2] * s0 + b0, c[mi][ni][3] * s1 + b1);
            *reinterpret_cast<float2*>(out + (size_t)r * N_TOTAL + col) = v0;
            *reinterpret_cast<float2*>(out + (size_t)(r + 8) * N_TOTAL + col) = v1;
        }
    }
}

// ============================================================================
// kernel_launch
// ============================================================================
extern "C" void kernel_launch(void* const* d_in, const int* in_sizes, int n_in,
                              void* d_out, int out_size) {
    const float* x     = (const float*)d_in[0];  // [4, 2048, 4096]
    const float* w_q   = (const float*)d_in[1];  // [11008, 4096]
    const float* scale = (const float*)d_in[2];  // [11008, 1]
    const float* bias  = (const float*)d_in[3];  // [11008]
    float* out = (float*)d_out;                  // [4, 2048, 11008]

    int n4x = M_TOTAL * (K_TOTAL / 4);           // 8,388,608
    int n4w = N_TOTAL * (K_TOTAL / 4);           // 11,272,192
    int n4 = n4x + n4w;
    k_prep<<<(n4 + 255) / 256, 256>>>((const float4*)x, (const float4*)w_q, n4x, n4w);

    cudaFuncSetAttribute(k_gemm, cudaFuncAttributeMaxDynamicSharedMemorySize, SMEM_BYTES);
    k_gemm<<<M_TILES * N_TILES, THREADS, SMEM_BYTES>>>(scale, bias, out);
}

// round 11
// speedup vs baseline: 1.0015x; 1.0008x over previous
#include <cuda_runtime.h>
#include <cuda_fp16.h>
#include <cstdint>

// ============================================================================
// Problem dims
// ============================================================================
static constexpr int M_TOTAL = 8192;      // B*S = 4*2048
static constexpr int N_TOTAL = 11008;     // D_OUT
static constexpr int K_TOTAL = 4096;      // D_IN

static constexpr int M_TILE = 128;
static constexpr int N_TILE = 128;
static constexpr int K_TILE = 64;         // 64 fp16 = 128B rows (SW128 atom)
static constexpr int STAGES = 3;
static constexpr int K_STEPS = K_TOTAL / K_TILE;   // 64
static constexpr int M_TILES = M_TOTAL / M_TILE;   // 64
static constexpr int N_TILES = N_TOTAL / N_TILE;   // 86
static constexpr int THREADS = 256;                // 8 warps: 2(m) x 4(n), warp tile 64x32

// SMEM stage: A 128x128B = 16KB, B 128x128B = 16KB
static constexpr int A_STAGE_BYTES = M_TILE * 128;           // 16384
static constexpr int B_STAGE_BYTES = N_TILE * 128;           // 16384
static constexpr int STAGE_BYTES = A_STAGE_BYTES + B_STAGE_BYTES;  // 32768
static constexpr int SMEM_BYTES = STAGES * STAGE_BYTES;      // 98304 -> 2 CTAs/SM

// ============================================================================
// Scratch (device globals — no allocation allowed)
// ============================================================================
__device__ __half g_xh[(size_t)M_TOTAL * K_TOTAL];   // 64 MB fp16 x
__device__ __half g_wh[(size_t)N_TOTAL * K_TOTAL];   // 86 MB fp16 w (exact from e4m3)

// ============================================================================
// Helpers
// ============================================================================
__device__ __forceinline__ uint32_t smem_to_u32(const void* p) {
    uint32_t a;
    asm("{ .reg .u64 t; cvta.to.shared.u64 t, %1; cvt.u32.u64 %0, t; }" : "=r"(a) : "l"(p));
    return a;
}

#define SW128(o) ((o) ^ (((o) >> 3) & 0x70))

__device__ __forceinline__ void cp_async16(uint32_t dst, const void* src) {
    unsigned long long g = (unsigned long long)__cvta_generic_to_global(src);
    asm volatile("cp.async.cg.shared.global [%0], [%1], 16;" :: "r"(dst), "l"(g) : "memory");
}
#define CP_COMMIT() asm volatile("cp.async.commit_group;" ::: "memory")
#define CP_WAIT_GROUP(n) asm volatile("cp.async.wait_group %0;" :: "n"(n) : "memory")

__device__ __forceinline__ void ldsm_x4(uint32_t& r0, uint32_t& r1, uint32_t& r2, uint32_t& r3,
                                        uint32_t addr) {
    asm volatile("ldmatrix.sync.aligned.m8n8.x4.shared.b16 {%0,%1,%2,%3}, [%4];"
                 : "=r"(r0), "=r"(r1), "=r"(r2), "=r"(r3) : "r"(addr));
}

__device__ __forceinline__ void mma_16816(float& c0, float& c1, float& c2, float& c3,
                                          uint32_t a0, uint32_t a1, uint32_t a2, uint32_t a3,
                                          uint32_t b0, uint32_t b1) {
    asm volatile("mma.sync.aligned.m16n8k16.row.col.f32.f16.f16.f32 "
                 "{%0,%1,%2,%3}, {%4,%5,%6,%7}, {%8,%9}, {%0,%1,%2,%3};"
                 : "+f"(c0), "+f"(c1), "+f"(c2), "+f"(c3)
                 : "r"(a0), "r"(a1), "r"(a2), "r"(a3), "r"(b0), "r"(b1));
}

// ============================================================================
// Merged prep: fp32 -> fp16 for x (rounds, rel <= 2^-11) and w (exact e4m3)
// ============================================================================
__global__ void k_prep(const float4* __restrict__ x, const float4* __restrict__ w,
                       int n4x, int n4w) {
    int i = blockIdx.x * 256 + threadIdx.x;
    const float4* src;
    uint2* dst;
    if (i < n4x) {
        src = x + i;
        dst = reinterpret_cast<uint2*>(g_xh) + i;
    } else {
        int j = i - n4x;
        if (j >= n4w) return;
        src = w + j;
        dst = reinterpret_cast<uint2*>(g_wh) + j;
    }
    float4 v = *src;
    union { __half h[4]; uint2 u; } p;
    p.h[0] = __float2half_rn(v.x); p.h[1] = __float2half_rn(v.y);
    p.h[2] = __float2half_rn(v.z); p.h[3] = __float2half_rn(v.w);
    *dst = p.u;
}

// ============================================================================
// GEMM: out[m,n] = sum_k x[m,k]*w[n,k] * scale[n] + bias[n]
// CTA tile 128x128, 8 warps (2m x 4n), warp tile 64x32, 2 CTAs/SM.
// ============================================================================
__global__ __launch_bounds__(THREADS, 2)
void k_gemm(const float* __restrict__ scale, const float* __restrict__ bias,
            float* __restrict__ out) {
    extern __shared__ char smem[];
    const uint32_t smem_u = smem_to_u32(smem);
    const int tid = threadIdx.x;
    const int lane = tid & 31;
    const int wid = tid >> 5;
    const int warp_m = wid >> 2;       // 0..1 -> 64-row slabs
    const int warp_n = wid & 3;        // 0..3 -> 32-col slabs

    // Tile mapping with GROUP=8 m-swizzle for L2 locality
    const int GROUP = 8;
    int bid = blockIdx.x;
    int tpg = GROUP * N_TILES;
    int g = bid / tpg;
    int rem = bid % tpg;
    const int m0 = (g * GROUP + (rem % GROUP)) * M_TILE;
    const int n0 = (rem / GROUP) * N_TILE;

    // ---- producer: fill stage (j % STAGES) with k-tile j ----
    auto produce = [&](int j) {
        const size_t k0 = (size_t)j * K_TILE;
        const uint32_t st = smem_u + (uint32_t)(j % STAGES) * STAGE_BYTES;
        // A: 128 rows x 8 16B-chunks = 1024 chunks, 4 per thread
#pragma unroll
        for (int q = 0; q < 4; q++) {
            int cid = tid + q * THREADS;
            int row = cid >> 3, ch = cid & 7;
            uint32_t off = SW128((uint32_t)(row * 128 + ch * 16));
            const char* s = (const char*)(g_xh + (size_t)(m0 + row) * K_TOTAL + k0) + ch * 16;
            cp_async16(st + off, s);
        }
        // B: 128 rows x 8 chunks = 1024 chunks, 4 per thread
#pragma unroll
        for (int q = 0; q < 4; q++) {
            int cid = tid + q * THREADS;
            int row = cid >> 3, ch = cid & 7;
            uint32_t off = SW128((uint32_t)(row * 128 + ch * 16));
            const char* s = (const char*)(g_wh + (size_t)(n0 + row) * K_TOTAL + k0) + ch * 16;
            cp_async16(st + (uint32_t)A_STAGE_BYTES + off, s);
        }
    };

    float c[4][4][4];   // [mi][ni][reg] = 64 regs
#pragma unroll
    for (int mi = 0; mi < 4; mi++)
#pragma unroll
        for (int ni = 0; ni < 4; ni++)
#pragma unroll
            for (int r = 0; r < 4; r++) c[mi][ni][r] = 0.0f;

    // prologue: fill 2 of 3 stages
    produce(0); CP_COMMIT();
    produce(1); CP_COMMIT();

    // Per-lane static pieces of ldmatrix addressing (validated in rounds 2-3)
    const int a_row_l = (lane & 7) + ((lane >> 3) & 1) * 8;   // within m16 tile
    const int a_kb_l  = ((lane >> 4) & 1) * 16;               // 0 or 16 bytes
    const int b_row_l = (lane & 7) + ((lane >> 4) & 1) * 8;   // within n16 block
    const int b_kb_l  = ((lane >> 3) & 1) * 16;

#pragma unroll 1
    for (int i = 0; i < K_STEPS; i++) {
        CP_WAIT_GROUP(1);        // k-tile i resident
        __syncthreads();         // all fills visible; all warps done with stage i-1

        int j = i + (STAGES - 1);
        if (j < K_STEPS) produce(j);
        CP_COMMIT();             // unconditional (possibly-empty group keeps count)

        const uint32_t stA = smem_u + (uint32_t)(i % STAGES) * STAGE_BYTES;
        const uint32_t stB = stA + (uint32_t)A_STAGE_BYTES;

#pragma unroll
        for (int ks = 0; ks < 4; ks++) {        // four k16 sub-steps in the 64-k tile
            uint32_t a[4][4];
#pragma unroll
            for (int mi = 0; mi < 4; mi++) {
                int row = warp_m * 64 + mi * 16 + a_row_l;
                uint32_t o = (uint32_t)(row * 128 + ks * 32 + a_kb_l);
                ldsm_x4(a[mi][0], a[mi][1], a[mi][2], a[mi][3], stA + SW128(o));
            }
            uint32_t b[2][4];
#pragma unroll
            for (int nb = 0; nb < 2; nb++) {
                int row = warp_n * 32 + nb * 16 + b_row_l;
                uint32_t o = (uint32_t)(row * 128 + ks * 32 + b_kb_l);
                ldsm_x4(b[nb][0], b[nb][1], b[nb][2], b[nb][3], stB + SW128(o));
            }
#pragma unroll
            for (int mi = 0; mi < 4; mi++) {
#pragma unroll
                for (int ni = 0; ni < 4; ni++) {
                    uint32_t b0 = b[ni >> 1][(ni & 1) * 2 + 0];
                    uint32_t b1 = b[ni >> 1][(ni & 1) * 2 + 1];
                    mma_16816(c[mi][ni][0], c[mi][ni][1], c[mi][ni][2], c[mi][ni][3],
                              a[mi][0], a[mi][1], a[mi][2], a[mi][3], b0, b1);
                }
            }
        }
    }

    // ---- epilogue: out = c * scale[n] + bias[n] ----
    const int col_base = n0 + warp_n * 32 + (lane & 3) * 2;
    const int row_base = m0 + warp_m * 64 + (lane >> 2);
#pragma unroll
    for (int ni = 0; ni < 4; ni++) {
        int col = col_base + ni * 8;
        float s0 = scale[col], s1 = scale[col + 1];
        float b0 = bias[col],  b1 = bias[col + 1];
#pragma unroll
        for (int mi = 0; mi < 4; mi++) {
            int r = row_base + mi * 16;
            float2 v0 = make_float2(c[mi][ni][0] * s0 + b0, c[mi][ni][1] * s1 + b1);
            float2 v1 = make_float2(c[mi][ni][2] * s0 + b0, c[mi][ni][3] * s1 + b1);
            *reinterpret_cast<float2*>(out + (size_t)r * N_TOTAL + col) = v0;
            *reinterpret_cast<float2*>(out + (size_t)(r + 8) * N_TOTAL + col) = v1;
        }
    }
}

// ============================================================================
// kernel_launch
// ============================================================================
extern "C" void kernel_launch(void* const* d_in, const int* in_sizes, int n_in,
                              void* d_out, int out_size) {
    const float* x     = (const float*)d_in[0];  // [4, 2048, 4096]
    const float* w_q   = (const float*)d_in[1];  // [11008, 4096]
    const float* scale = (const float*)d_in[2];  // [11008, 1]
    const float* bias  = (const float*)d_in[3];  // [11008]
    float* out = (float*)d_out;                  // [4, 2048, 11008]

    int n4x = M_TOTAL * (K_TOTAL / 4);           // 8,388,608
    int n4w = N_TOTAL * (K_TOTAL / 4);           // 11,272,192
    int n4 = n4x + n4w;
    k_prep<<<(n4 + 255) / 256, 256>>>((const float4*)x, (const float4*)w_q, n4x, n4w);

    cudaFuncSetAttribute(k_gemm, cudaFuncAttributeMaxDynamicSharedMemorySize, SMEM_BYTES);
    k_gemm<<<M_TILES * N_TILES, THREADS, SMEM_BYTES>>>(scale, bias, out);
}